// round 8
// baseline (speedup 1.0000x reference)
#include <cuda_runtime.h>

// out = x[0]; out[c, ix, iy] += img[c, proj_y, proj_x]
// Channel-split position-major scratch (each half: imgT_h 32MB + accT_h 32MB,
// L2-resident). Overlapped phases (R7) + L2 cache-policy hints (R8):
// streaming traffic (__ldcs/__stcs) must not evict the scatter's resident set.
//   A: prep half0
//   B: scatter half0 || prep half1 (prep1 stores streaming)
//   C: scatter half1 || finish half0
//   D: finish half1

#define HW (1024 * 1024)

__device__ float g_imgT0[(size_t)HW * 8];
__device__ float g_imgT1[(size_t)HW * 8];
__device__ float g_accT0[(size_t)HW * 8];
__device__ float g_accT1[(size_t)HW * 8];

__device__ __forceinline__ void red_add_v4(float* ptr, float4 v) {
    asm volatile("red.global.add.v4.f32 [%0], {%1, %2, %3, %4};"
                 :: "l"(ptr), "f"(v.x), "f"(v.y), "f"(v.z), "f"(v.w)
                 : "memory");
}

// ---- role bodies (block-level) ------------------------------------------

// Transpose 8 channels [8h, 8h+8) of x and img into accT_h / imgT_h.
// Sources are read once -> __ldcs. STREAM_ST: stores also streaming (used in
// kB so prep1 doesn't evict scatter0's hot set).
template <int HALF, bool STREAM_ST>
__device__ __forceinline__ void prep_block(const float* __restrict__ x,
                                           const float* __restrict__ img,
                                           int pb, int tid) {
    float* __restrict__ accTh = (HALF == 0) ? g_accT0 : g_accT1;
    float* __restrict__ imgTh = (HALF == 0) ? g_imgT0 : g_imgT1;
    const size_t choff = (size_t)(HALF * 8) * HW;

    int p2 = (pb * 256 + tid) * 2;
    if (p2 >= HW) return;

    float2 r[8];
#pragma unroll
    for (int c = 0; c < 8; c++)
        r[c] = __ldcs((const float2*)(x + choff + (size_t)c * HW + p2));
    float4* d = (float4*)(accTh + (size_t)p2 * 8);
    float4 w0 = make_float4(r[0].x, r[1].x, r[2].x, r[3].x);
    float4 w1 = make_float4(r[4].x, r[5].x, r[6].x, r[7].x);
    float4 w2 = make_float4(r[0].y, r[1].y, r[2].y, r[3].y);
    float4 w3 = make_float4(r[4].y, r[5].y, r[6].y, r[7].y);
    if (STREAM_ST) { __stcs(d+0, w0); __stcs(d+1, w1); __stcs(d+2, w2); __stcs(d+3, w3); }
    else           { d[0] = w0; d[1] = w1; d[2] = w2; d[3] = w3; }

#pragma unroll
    for (int c = 0; c < 8; c++)
        r[c] = __ldcs((const float2*)(img + choff + (size_t)c * HW + p2));
    float4* e = (float4*)(imgTh + (size_t)p2 * 8);
    w0 = make_float4(r[0].x, r[1].x, r[2].x, r[3].x);
    w1 = make_float4(r[4].x, r[5].x, r[6].x, r[7].x);
    w2 = make_float4(r[0].y, r[1].y, r[2].y, r[3].y);
    w3 = make_float4(r[4].y, r[5].y, r[6].y, r[7].y);
    if (STREAM_ST) { __stcs(e+0, w0); __stcs(e+1, w1); __stcs(e+2, w2); __stcs(e+3, w3); }
    else           { e[0] = w0; e[1] = w1; e[2] = w2; e[3] = w3; }
}

// Scatter-add 4 records per thread within one half. Index loads streaming.
template <int HALF>
__device__ __forceinline__ void scatter_block(const int* __restrict__ index_x,
                                              const int* __restrict__ index_y,
                                              const int* __restrict__ proj_x,
                                              const int* __restrict__ proj_y,
                                              int L, int sb, int tid) {
    const float* __restrict__ imgTh = (HALF == 0) ? g_imgT0 : g_imgT1;
    float* __restrict__ accTh       = (HALF == 0) ? g_accT0 : g_accT1;

    int l4 = (sb * 256 + tid) * 4;
    if (l4 + 3 < L) {
        int4 ix = __ldcs((const int4*)(index_x + l4));
        int4 iy = __ldcs((const int4*)(index_y + l4));
        int4 px = __ldcs((const int4*)(proj_x + l4));
        int4 py = __ldcs((const int4*)(proj_y + l4));

        int s0 = py.x * 1024 + px.x, d0 = ix.x * 1024 + iy.x;
        int s1 = py.y * 1024 + px.y, d1 = ix.y * 1024 + iy.y;
        int s2 = py.z * 1024 + px.z, d2 = ix.z * 1024 + iy.z;
        int s3 = py.w * 1024 + px.w, d3 = ix.w * 1024 + iy.w;

        const float4* g0 = (const float4*)(imgTh + (size_t)s0 * 8);
        const float4* g1 = (const float4*)(imgTh + (size_t)s1 * 8);
        const float4* g2 = (const float4*)(imgTh + (size_t)s2 * 8);
        const float4* g3 = (const float4*)(imgTh + (size_t)s3 * 8);
        float4 a0 = __ldg(g0 + 0), a1 = __ldg(g0 + 1);
        float4 b0 = __ldg(g1 + 0), b1 = __ldg(g1 + 1);
        float4 c0 = __ldg(g2 + 0), c1 = __ldg(g2 + 1);
        float4 e0 = __ldg(g3 + 0), e1 = __ldg(g3 + 1);

        float* w0 = accTh + (size_t)d0 * 8;
        float* w1 = accTh + (size_t)d1 * 8;
        float* w2 = accTh + (size_t)d2 * 8;
        float* w3 = accTh + (size_t)d3 * 8;
        red_add_v4(w0 + 0, a0); red_add_v4(w0 + 4, a1);
        red_add_v4(w1 + 0, b0); red_add_v4(w1 + 4, b1);
        red_add_v4(w2 + 0, c0); red_add_v4(w2 + 4, c1);
        red_add_v4(w3 + 0, e0); red_add_v4(w3 + 4, e1);
    } else {
        for (int l = l4; l < L; l++) {
            int src = __ldg(proj_y + l) * 1024 + __ldg(proj_x + l);
            int dst = __ldg(index_x + l) * 1024 + __ldg(index_y + l);
            const float4* s = (const float4*)(imgTh + (size_t)src * 8);
            float4 v0 = __ldg(s + 0);
            float4 v1 = __ldg(s + 1);
            float* d = accTh + (size_t)dst * 8;
            red_add_v4(d + 0, v0);
            red_add_v4(d + 4, v1);
        }
    }
}

// Write out channels [8h, 8h+8) from accT_h. Reads once, writes never re-read:
// full streaming policy.
template <int HALF>
__device__ __forceinline__ void finish_block(float* __restrict__ out,
                                             int fb, int tid) {
    const float* __restrict__ accTh = (HALF == 0) ? g_accT0 : g_accT1;
    const size_t choff = (size_t)(HALF * 8) * HW;

    int p2 = (fb * 256 + tid) * 2;
    if (p2 >= HW) return;

    float4 v[4];
    const float4* a = (const float4*)(accTh + (size_t)p2 * 8);
#pragma unroll
    for (int i = 0; i < 4; i++) v[i] = __ldcs(a + i);
    const float* f = (const float*)v;  // f[j*8 + c] = acc[p2+j][c]
#pragma unroll
    for (int c = 0; c < 8; c++) {
        __stcs((float2*)(out + choff + (size_t)c * HW + p2),
               make_float2(f[c], f[8 + c]));
    }
}

// ---- kernels --------------------------------------------------------------

#define NPREP  (HW / 2 / 256)   // 2048 blocks per half-prep / half-finish

__global__ void __launch_bounds__(256) kA_prep0(const float* __restrict__ x,
                                                const float* __restrict__ img) {
    prep_block<0, false>(x, img, blockIdx.x, threadIdx.x);
}

// B: scatter half0 (2 of every 3 blocks) || prep half1 (1 of every 3, streaming stores)
__global__ void __launch_bounds__(256) kB(const float* __restrict__ x,
                                          const float* __restrict__ img,
                                          const int* __restrict__ index_x,
                                          const int* __restrict__ index_y,
                                          const int* __restrict__ proj_x,
                                          const int* __restrict__ proj_y,
                                          int L, int NS) {
    int g = blockIdx.x / 3, r = blockIdx.x % 3;
    if (r < 2) {
        int sb = g * 2 + r;
        if (sb < NS) scatter_block<0>(index_x, index_y, proj_x, proj_y, L, sb, threadIdx.x);
    } else {
        if (g < NPREP) prep_block<1, true>(x, img, g, threadIdx.x);
    }
}

// C: scatter half1 || finish half0
__global__ void __launch_bounds__(256) kC(float* __restrict__ out,
                                          const int* __restrict__ index_x,
                                          const int* __restrict__ index_y,
                                          const int* __restrict__ proj_x,
                                          const int* __restrict__ proj_y,
                                          int L, int NS) {
    int g = blockIdx.x / 3, r = blockIdx.x % 3;
    if (r < 2) {
        int sb = g * 2 + r;
        if (sb < NS) scatter_block<1>(index_x, index_y, proj_x, proj_y, L, sb, threadIdx.x);
    } else {
        if (g < NPREP) finish_block<0>(out, g, threadIdx.x);
    }
}

__global__ void __launch_bounds__(256) kD_finish1(float* __restrict__ out) {
    finish_block<1>(out, blockIdx.x, threadIdx.x);
}

extern "C" void kernel_launch(void* const* d_in, const int* in_sizes, int n_in,
                              void* d_out, int out_size) {
    const float* x       = (const float*)d_in[0];
    const float* img     = (const float*)d_in[1];
    const int*   index_x = (const int*)d_in[2];
    const int*   index_y = (const int*)d_in[3];
    const int*   proj_x  = (const int*)d_in[4];
    const int*   proj_y  = (const int*)d_in[5];
    float*       out     = (float*)d_out;

    const int L = in_sizes[2];

    int NS = (L / 4 + 255) / 256 + 1;                 // scatter blocks (tail-safe)
    int groups = ((NS + 1) / 2 > NPREP) ? (NS + 1) / 2 : NPREP;
    int NB = 3 * groups;

    kA_prep0<<<NPREP, 256>>>(x, img);
    kB<<<NB, 256>>>(x, img, index_x, index_y, proj_x, proj_y, L, NS);
    kC<<<NB, 256>>>(out, index_x, index_y, proj_x, proj_y, L, NS);
    kD_finish1<<<NPREP, 256>>>(out);
}

// round 9
// speedup vs baseline: 1.2360x; 1.2360x over previous
#include <cuda_runtime.h>

// out = x[0]; out[c, ix, iy] += img[c, proj_y, proj_x]
// Channel-split position-major scratch (each half: imgT_h 32MB + accT_h 32MB,
// L2-resident). Overlapped phases (R7 structure, default cache policy —
// R8 proved .cs hints destroy the L2 pre-warm):
//   A: prep half0
//   B: scatter half0 || prep half1   (4:1 block interleave)
//   C: scatter half1 || finish half0 (4:1)
//   D: finish half1
// R9: prep/finish widened to 4 positions/thread (float4 both sides, phased
// to cap live registers at ~32 floats).

#define HW (1024 * 1024)

__device__ float g_imgT0[(size_t)HW * 8];
__device__ float g_imgT1[(size_t)HW * 8];
__device__ float g_accT0[(size_t)HW * 8];
__device__ float g_accT1[(size_t)HW * 8];

__device__ __forceinline__ void red_add_v4(float* ptr, float4 v) {
    asm volatile("red.global.add.v4.f32 [%0], {%1, %2, %3, %4};"
                 :: "l"(ptr), "f"(v.x), "f"(v.y), "f"(v.z), "f"(v.w)
                 : "memory");
}

// ---- role bodies (block-level) ------------------------------------------

// Transpose 8 channels of one source tensor for 4 consecutive positions into
// a position-major dest. 8 float4 loads (coalesced), 8 float4 stores
// (128 B contiguous x2 per thread). ~32 floats live.
__device__ __forceinline__ void prep_quad(const float* __restrict__ src,
                                          float* __restrict__ dstT,
                                          int p4) {
    float4 r[8];
#pragma unroll
    for (int c = 0; c < 8; c++)
        r[c] = __ldg((const float4*)(src + (size_t)c * HW + p4));
    float4* d = (float4*)(dstT + (size_t)p4 * 8);
    d[0] = make_float4(r[0].x, r[1].x, r[2].x, r[3].x);
    d[1] = make_float4(r[4].x, r[5].x, r[6].x, r[7].x);
    d[2] = make_float4(r[0].y, r[1].y, r[2].y, r[3].y);
    d[3] = make_float4(r[4].y, r[5].y, r[6].y, r[7].y);
    d[4] = make_float4(r[0].z, r[1].z, r[2].z, r[3].z);
    d[5] = make_float4(r[4].z, r[5].z, r[6].z, r[7].z);
    d[6] = make_float4(r[0].w, r[1].w, r[2].w, r[3].w);
    d[7] = make_float4(r[4].w, r[5].w, r[6].w, r[7].w);
}

// Prep one half: x chans [8h,8h+8) -> accT_h, img chans -> imgT_h.
// Phased (x fully, then img) so register peak stays at one prep_quad.
template <int HALF>
__device__ __forceinline__ void prep_block(const float* __restrict__ x,
                                           const float* __restrict__ img,
                                           int pb, int tid) {
    float* __restrict__ accTh = (HALF == 0) ? g_accT0 : g_accT1;
    float* __restrict__ imgTh = (HALF == 0) ? g_imgT0 : g_imgT1;
    const size_t choff = (size_t)(HALF * 8) * HW;

    int p4 = (pb * 256 + tid) * 4;
    if (p4 >= HW) return;
    prep_quad(x + choff,   accTh, p4);
    prep_quad(img + choff, imgTh, p4);
}

// Scatter-add 4 records per thread within one half (proven R6/R7 body).
template <int HALF>
__device__ __forceinline__ void scatter_block(const int* __restrict__ index_x,
                                              const int* __restrict__ index_y,
                                              const int* __restrict__ proj_x,
                                              const int* __restrict__ proj_y,
                                              int L, int sb, int tid) {
    const float* __restrict__ imgTh = (HALF == 0) ? g_imgT0 : g_imgT1;
    float* __restrict__ accTh       = (HALF == 0) ? g_accT0 : g_accT1;

    int l4 = (sb * 256 + tid) * 4;
    if (l4 + 3 < L) {
        int4 ix = __ldg((const int4*)(index_x + l4));
        int4 iy = __ldg((const int4*)(index_y + l4));
        int4 px = __ldg((const int4*)(proj_x + l4));
        int4 py = __ldg((const int4*)(proj_y + l4));

        int s0 = py.x * 1024 + px.x, d0 = ix.x * 1024 + iy.x;
        int s1 = py.y * 1024 + px.y, d1 = ix.y * 1024 + iy.y;
        int s2 = py.z * 1024 + px.z, d2 = ix.z * 1024 + iy.z;
        int s3 = py.w * 1024 + px.w, d3 = ix.w * 1024 + iy.w;

        const float4* g0 = (const float4*)(imgTh + (size_t)s0 * 8);
        const float4* g1 = (const float4*)(imgTh + (size_t)s1 * 8);
        const float4* g2 = (const float4*)(imgTh + (size_t)s2 * 8);
        const float4* g3 = (const float4*)(imgTh + (size_t)s3 * 8);
        float4 a0 = __ldg(g0 + 0), a1 = __ldg(g0 + 1);
        float4 b0 = __ldg(g1 + 0), b1 = __ldg(g1 + 1);
        float4 c0 = __ldg(g2 + 0), c1 = __ldg(g2 + 1);
        float4 e0 = __ldg(g3 + 0), e1 = __ldg(g3 + 1);

        float* w0 = accTh + (size_t)d0 * 8;
        float* w1 = accTh + (size_t)d1 * 8;
        float* w2 = accTh + (size_t)d2 * 8;
        float* w3 = accTh + (size_t)d3 * 8;
        red_add_v4(w0 + 0, a0); red_add_v4(w0 + 4, a1);
        red_add_v4(w1 + 0, b0); red_add_v4(w1 + 4, b1);
        red_add_v4(w2 + 0, c0); red_add_v4(w2 + 4, c1);
        red_add_v4(w3 + 0, e0); red_add_v4(w3 + 4, e1);
    } else {
        for (int l = l4; l < L; l++) {
            int src = __ldg(proj_y + l) * 1024 + __ldg(proj_x + l);
            int dst = __ldg(index_x + l) * 1024 + __ldg(index_y + l);
            const float4* s = (const float4*)(imgTh + (size_t)src * 8);
            float4 v0 = __ldg(s + 0);
            float4 v1 = __ldg(s + 1);
            float* d = accTh + (size_t)dst * 8;
            red_add_v4(d + 0, v0);
            red_add_v4(d + 4, v1);
        }
    }
}

// Write out channels [8h,8h+8) from accT_h, 4 positions/thread.
// Reads 2x128 B contiguous; writes one float4 per channel (coalesced 16 B).
template <int HALF>
__device__ __forceinline__ void finish_block(float* __restrict__ out,
                                             int fb, int tid) {
    const float* __restrict__ accTh = (HALF == 0) ? g_accT0 : g_accT1;
    const size_t choff = (size_t)(HALF * 8) * HW;

    int p4 = (fb * 256 + tid) * 4;
    if (p4 >= HW) return;

    float4 v[8];
    const float4* a = (const float4*)(accTh + (size_t)p4 * 8);
#pragma unroll
    for (int i = 0; i < 8; i++) v[i] = a[i];
    const float* f = (const float*)v;  // f[j*8 + c] = acc[p4+j][c]
#pragma unroll
    for (int c = 0; c < 8; c++) {
        *(float4*)(out + choff + (size_t)c * HW + p4) =
            make_float4(f[0*8+c], f[1*8+c], f[2*8+c], f[3*8+c]);
    }
}

// ---- kernels --------------------------------------------------------------

#define NPREP4  (HW / 4 / 256)   // 1024 blocks per half prep/finish

__global__ void __launch_bounds__(256) kA_prep0(const float* __restrict__ x,
                                                const float* __restrict__ img) {
    prep_block<0>(x, img, blockIdx.x, threadIdx.x);
}

// B: scatter half0 (4 of every 5 blocks) || prep half1 (1 of every 5)
__global__ void __launch_bounds__(256) kB(const float* __restrict__ x,
                                          const float* __restrict__ img,
                                          const int* __restrict__ index_x,
                                          const int* __restrict__ index_y,
                                          const int* __restrict__ proj_x,
                                          const int* __restrict__ proj_y,
                                          int L, int NS) {
    int g = blockIdx.x / 5, r = blockIdx.x % 5;
    if (r < 4) {
        int sb = g * 4 + r;
        if (sb < NS) scatter_block<0>(index_x, index_y, proj_x, proj_y, L, sb, threadIdx.x);
    } else {
        if (g < NPREP4) prep_block<1>(x, img, g, threadIdx.x);
    }
}

// C: scatter half1 || finish half0
__global__ void __launch_bounds__(256) kC(float* __restrict__ out,
                                          const int* __restrict__ index_x,
                                          const int* __restrict__ index_y,
                                          const int* __restrict__ proj_x,
                                          const int* __restrict__ proj_y,
                                          int L, int NS) {
    int g = blockIdx.x / 5, r = blockIdx.x % 5;
    if (r < 4) {
        int sb = g * 4 + r;
        if (sb < NS) scatter_block<1>(index_x, index_y, proj_x, proj_y, L, sb, threadIdx.x);
    } else {
        if (g < NPREP4) finish_block<0>(out, g, threadIdx.x);
    }
}

__global__ void __launch_bounds__(256) kD_finish1(float* __restrict__ out) {
    finish_block<1>(out, blockIdx.x, threadIdx.x);
}

extern "C" void kernel_launch(void* const* d_in, const int* in_sizes, int n_in,
                              void* d_out, int out_size) {
    const float* x       = (const float*)d_in[0];
    const float* img     = (const float*)d_in[1];
    const int*   index_x = (const int*)d_in[2];
    const int*   index_y = (const int*)d_in[3];
    const int*   proj_x  = (const int*)d_in[4];
    const int*   proj_y  = (const int*)d_in[5];
    float*       out     = (float*)d_out;

    const int L = in_sizes[2];

    int NS = (L / 4 + 255) / 256 + 1;                 // scatter blocks (tail-safe)
    int g4 = (NS + 3) / 4;
    int groups = (g4 > NPREP4) ? g4 : NPREP4;
    int NB = 5 * groups;

    kA_prep0<<<NPREP4, 256>>>(x, img);
    kB<<<NB, 256>>>(x, img, index_x, index_y, proj_x, proj_y, L, NS);
    kC<<<NB, 256>>>(out, index_x, index_y, proj_x, proj_y, L, NS);
    kD_finish1<<<NPREP4, 256>>>(out);
}

// round 10
// speedup vs baseline: 1.4093x; 1.1402x over previous
#include <cuda_runtime.h>

// out = x[0]; out[c, ix, iy] += img[c, proj_y, proj_x]
// Channel-split position-major scratch (each half: imgT_h 32MB + accT_h 32MB,
// L2-resident). R10 = R7 bodies (proven optimal) with asymmetric overlap:
//   A: prep half0
//   B: scatter half0 || prep half1 (2:1) -- profitable (pollution = pre-warm)
//   C: scatter half1 SOLO              -- overlap with finish0 was a net loss
//   D: finish half0 + half1 (fused, parity-interleaved)

#define HW (1024 * 1024)

__device__ float g_imgT0[(size_t)HW * 8];
__device__ float g_imgT1[(size_t)HW * 8];
__device__ float g_accT0[(size_t)HW * 8];
__device__ float g_accT1[(size_t)HW * 8];

__device__ __forceinline__ void red_add_v4(float* ptr, float4 v) {
    asm volatile("red.global.add.v4.f32 [%0], {%1, %2, %3, %4};"
                 :: "l"(ptr), "f"(v.x), "f"(v.y), "f"(v.z), "f"(v.w)
                 : "memory");
}

// ---- role bodies (R7-proven) ----------------------------------------------

// Transpose 8 channels [8h, 8h+8) of x and img into accT_h / imgT_h.
// 2 positions per thread, float2 loads, float4 stores.
template <int HALF>
__device__ __forceinline__ void prep_block(const float* __restrict__ x,
                                           const float* __restrict__ img,
                                           int pb, int tid) {
    float* __restrict__ accTh = (HALF == 0) ? g_accT0 : g_accT1;
    float* __restrict__ imgTh = (HALF == 0) ? g_imgT0 : g_imgT1;
    const size_t choff = (size_t)(HALF * 8) * HW;

    int p2 = (pb * 256 + tid) * 2;
    if (p2 >= HW) return;

    float2 r[8];
#pragma unroll
    for (int c = 0; c < 8; c++)
        r[c] = __ldg((const float2*)(x + choff + (size_t)c * HW + p2));
    float4* d = (float4*)(accTh + (size_t)p2 * 8);
    d[0] = make_float4(r[0].x, r[1].x, r[2].x, r[3].x);
    d[1] = make_float4(r[4].x, r[5].x, r[6].x, r[7].x);
    d[2] = make_float4(r[0].y, r[1].y, r[2].y, r[3].y);
    d[3] = make_float4(r[4].y, r[5].y, r[6].y, r[7].y);

#pragma unroll
    for (int c = 0; c < 8; c++)
        r[c] = __ldg((const float2*)(img + choff + (size_t)c * HW + p2));
    float4* e = (float4*)(imgTh + (size_t)p2 * 8);
    e[0] = make_float4(r[0].x, r[1].x, r[2].x, r[3].x);
    e[1] = make_float4(r[4].x, r[5].x, r[6].x, r[7].x);
    e[2] = make_float4(r[0].y, r[1].y, r[2].y, r[3].y);
    e[3] = make_float4(r[4].y, r[5].y, r[6].y, r[7].y);
}

// Scatter-add 4 records per thread within one half.
template <int HALF>
__device__ __forceinline__ void scatter_block(const int* __restrict__ index_x,
                                              const int* __restrict__ index_y,
                                              const int* __restrict__ proj_x,
                                              const int* __restrict__ proj_y,
                                              int L, int sb, int tid) {
    const float* __restrict__ imgTh = (HALF == 0) ? g_imgT0 : g_imgT1;
    float* __restrict__ accTh       = (HALF == 0) ? g_accT0 : g_accT1;

    int l4 = (sb * 256 + tid) * 4;
    if (l4 + 3 < L) {
        int4 ix = __ldg((const int4*)(index_x + l4));
        int4 iy = __ldg((const int4*)(index_y + l4));
        int4 px = __ldg((const int4*)(proj_x + l4));
        int4 py = __ldg((const int4*)(proj_y + l4));

        int s0 = py.x * 1024 + px.x, d0 = ix.x * 1024 + iy.x;
        int s1 = py.y * 1024 + px.y, d1 = ix.y * 1024 + iy.y;
        int s2 = py.z * 1024 + px.z, d2 = ix.z * 1024 + iy.z;
        int s3 = py.w * 1024 + px.w, d3 = ix.w * 1024 + iy.w;

        const float4* g0 = (const float4*)(imgTh + (size_t)s0 * 8);
        const float4* g1 = (const float4*)(imgTh + (size_t)s1 * 8);
        const float4* g2 = (const float4*)(imgTh + (size_t)s2 * 8);
        const float4* g3 = (const float4*)(imgTh + (size_t)s3 * 8);
        float4 a0 = __ldg(g0 + 0), a1 = __ldg(g0 + 1);
        float4 b0 = __ldg(g1 + 0), b1 = __ldg(g1 + 1);
        float4 c0 = __ldg(g2 + 0), c1 = __ldg(g2 + 1);
        float4 e0 = __ldg(g3 + 0), e1 = __ldg(g3 + 1);

        float* w0 = accTh + (size_t)d0 * 8;
        float* w1 = accTh + (size_t)d1 * 8;
        float* w2 = accTh + (size_t)d2 * 8;
        float* w3 = accTh + (size_t)d3 * 8;
        red_add_v4(w0 + 0, a0); red_add_v4(w0 + 4, a1);
        red_add_v4(w1 + 0, b0); red_add_v4(w1 + 4, b1);
        red_add_v4(w2 + 0, c0); red_add_v4(w2 + 4, c1);
        red_add_v4(w3 + 0, e0); red_add_v4(w3 + 4, e1);
    } else {
        for (int l = l4; l < L; l++) {
            int src = __ldg(proj_y + l) * 1024 + __ldg(proj_x + l);
            int dst = __ldg(index_x + l) * 1024 + __ldg(index_y + l);
            const float4* s = (const float4*)(imgTh + (size_t)src * 8);
            float4 v0 = __ldg(s + 0);
            float4 v1 = __ldg(s + 1);
            float* d = accTh + (size_t)dst * 8;
            red_add_v4(d + 0, v0);
            red_add_v4(d + 4, v1);
        }
    }
}

// Write out channels [8h, 8h+8) from accT_h. 2 positions/thread.
template <int HALF>
__device__ __forceinline__ void finish_block(float* __restrict__ out,
                                             int fb, int tid) {
    const float* __restrict__ accTh = (HALF == 0) ? g_accT0 : g_accT1;
    const size_t choff = (size_t)(HALF * 8) * HW;

    int p2 = (fb * 256 + tid) * 2;
    if (p2 >= HW) return;

    float4 v[4];
    const float4* a = (const float4*)(accTh + (size_t)p2 * 8);
#pragma unroll
    for (int i = 0; i < 4; i++) v[i] = a[i];
    const float* f = (const float*)v;  // f[j*8 + c] = acc[p2+j][c]
#pragma unroll
    for (int c = 0; c < 8; c++) {
        *(float2*)(out + choff + (size_t)c * HW + p2) =
            make_float2(f[c], f[8 + c]);
    }
}

// ---- kernels --------------------------------------------------------------

#define NPREP  (HW / 2 / 256)   // 2048 blocks per half-prep / half-finish

__global__ void __launch_bounds__(256) kA_prep0(const float* __restrict__ x,
                                                const float* __restrict__ img) {
    prep_block<0>(x, img, blockIdx.x, threadIdx.x);
}

// B: scatter half0 (2 of every 3 blocks) || prep half1 (1 of every 3)
__global__ void __launch_bounds__(256) kB(const float* __restrict__ x,
                                          const float* __restrict__ img,
                                          const int* __restrict__ index_x,
                                          const int* __restrict__ index_y,
                                          const int* __restrict__ proj_x,
                                          const int* __restrict__ proj_y,
                                          int L, int NS) {
    int g = blockIdx.x / 3, r = blockIdx.x % 3;
    if (r < 2) {
        int sb = g * 2 + r;
        if (sb < NS) scatter_block<0>(index_x, index_y, proj_x, proj_y, L, sb, threadIdx.x);
    } else {
        if (g < NPREP) prep_block<1>(x, img, g, threadIdx.x);
    }
}

// C: scatter half1 solo (L2 pre-warmed by kB's prep1)
__global__ void __launch_bounds__(256) kC_scatter1(const int* __restrict__ index_x,
                                                   const int* __restrict__ index_y,
                                                   const int* __restrict__ proj_x,
                                                   const int* __restrict__ proj_y,
                                                   int L) {
    scatter_block<1>(index_x, index_y, proj_x, proj_y, L, blockIdx.x, threadIdx.x);
}

// D: finish both halves, parity-interleaved.
__global__ void __launch_bounds__(256) kD_finish(float* __restrict__ out) {
    int g = blockIdx.x >> 1;
    if (blockIdx.x & 1) finish_block<1>(out, g, threadIdx.x);
    else                finish_block<0>(out, g, threadIdx.x);
}

extern "C" void kernel_launch(void* const* d_in, const int* in_sizes, int n_in,
                              void* d_out, int out_size) {
    const float* x       = (const float*)d_in[0];
    const float* img     = (const float*)d_in[1];
    const int*   index_x = (const int*)d_in[2];
    const int*   index_y = (const int*)d_in[3];
    const int*   proj_x  = (const int*)d_in[4];
    const int*   proj_y  = (const int*)d_in[5];
    float*       out     = (float*)d_out;

    const int L = in_sizes[2];

    int NS = (L / 4 + 255) / 256 + 1;                 // scatter blocks (tail-safe)
    int groups = ((NS + 1) / 2 > NPREP) ? (NS + 1) / 2 : NPREP;
    int NB = 3 * groups;

    kA_prep0<<<NPREP, 256>>>(x, img);
    kB<<<NB, 256>>>(x, img, index_x, index_y, proj_x, proj_y, L, NS);
    kC_scatter1<<<NS, 256>>>(index_x, index_y, proj_x, proj_y, L);
    kD_finish<<<2 * NPREP, 256>>>(out);
}

// round 11
// speedup vs baseline: 1.6117x; 1.1436x over previous
#include <cuda_runtime.h>
#include <cuda_fp16.h>

// out = x[0]; out[c, ix, iy] += img[c, proj_y, proj_x]
// Channel-split position-major scratch. R11: gather payload (imgT) stored as
// fp16 (16 B per record-half) -> per-pass L2 working set 48MB instead of
// 64MB; accumulator stays f32 (exact copy path). Overlap structure = R10:
//   A: prep half0
//   B: scatter half0 || prep half1 (2:1)
//   C: scatter half1 solo
//   D: finish half0 + half1 (parity-interleaved)

#define HW (1024 * 1024)

__device__ __half g_imgT0[(size_t)HW * 8];
__device__ __half g_imgT1[(size_t)HW * 8];
__device__ float  g_accT0[(size_t)HW * 8];
__device__ float  g_accT1[(size_t)HW * 8];

__device__ __forceinline__ void red_add_v4(float* ptr, float4 v) {
    asm volatile("red.global.add.v4.f32 [%0], {%1, %2, %3, %4};"
                 :: "l"(ptr), "f"(v.x), "f"(v.y), "f"(v.z), "f"(v.w)
                 : "memory");
}

// ---- role bodies ------------------------------------------------------------

// Transpose 8 channels [8h, 8h+8): x -> accT_h (f32), img -> imgT_h (f16).
// 2 positions per thread, float2 loads.
template <int HALF>
__device__ __forceinline__ void prep_block(const float* __restrict__ x,
                                           const float* __restrict__ img,
                                           int pb, int tid) {
    float*  __restrict__ accTh = (HALF == 0) ? g_accT0 : g_accT1;
    __half* __restrict__ imgTh = (HALF == 0) ? g_imgT0 : g_imgT1;
    const size_t choff = (size_t)(HALF * 8) * HW;

    int p2 = (pb * 256 + tid) * 2;
    if (p2 >= HW) return;

    float2 r[8];
#pragma unroll
    for (int c = 0; c < 8; c++)
        r[c] = __ldg((const float2*)(x + choff + (size_t)c * HW + p2));
    float4* d = (float4*)(accTh + (size_t)p2 * 8);
    d[0] = make_float4(r[0].x, r[1].x, r[2].x, r[3].x);
    d[1] = make_float4(r[4].x, r[5].x, r[6].x, r[7].x);
    d[2] = make_float4(r[0].y, r[1].y, r[2].y, r[3].y);
    d[3] = make_float4(r[4].y, r[5].y, r[6].y, r[7].y);

#pragma unroll
    for (int c = 0; c < 8; c++)
        r[c] = __ldg((const float2*)(img + choff + (size_t)c * HW + p2));
    // position p2:   halves of r[c].x ; position p2+1: halves of r[c].y
    __half2 h[8];
    h[0] = __floats2half2_rn(r[0].x, r[1].x);
    h[1] = __floats2half2_rn(r[2].x, r[3].x);
    h[2] = __floats2half2_rn(r[4].x, r[5].x);
    h[3] = __floats2half2_rn(r[6].x, r[7].x);
    h[4] = __floats2half2_rn(r[0].y, r[1].y);
    h[5] = __floats2half2_rn(r[2].y, r[3].y);
    h[6] = __floats2half2_rn(r[4].y, r[5].y);
    h[7] = __floats2half2_rn(r[6].y, r[7].y);
    // 2 positions x 16 B = one 32 B contiguous store pair
    *(uint4*)(imgTh + (size_t)p2 * 8)       = *(const uint4*)&h[0];
    *(uint4*)(imgTh + (size_t)(p2 + 1) * 8) = *(const uint4*)&h[4];
}

__device__ __forceinline__ void gather_add(const __half* __restrict__ imgTh,
                                           float* __restrict__ accTh,
                                           int src, int dst) {
    uint4 raw = __ldg((const uint4*)(imgTh + (size_t)src * 8));
    const __half2* h = (const __half2*)&raw;
    float2 f0 = __half22float2(h[0]);
    float2 f1 = __half22float2(h[1]);
    float2 f2 = __half22float2(h[2]);
    float2 f3 = __half22float2(h[3]);
    float* d = accTh + (size_t)dst * 8;
    red_add_v4(d + 0, make_float4(f0.x, f0.y, f1.x, f1.y));
    red_add_v4(d + 4, make_float4(f2.x, f2.y, f3.x, f3.y));
}

// Scatter-add 4 records per thread within one half.
template <int HALF>
__device__ __forceinline__ void scatter_block(const int* __restrict__ index_x,
                                              const int* __restrict__ index_y,
                                              const int* __restrict__ proj_x,
                                              const int* __restrict__ proj_y,
                                              int L, int sb, int tid) {
    const __half* __restrict__ imgTh = (HALF == 0) ? g_imgT0 : g_imgT1;
    float* __restrict__ accTh        = (HALF == 0) ? g_accT0 : g_accT1;

    int l4 = (sb * 256 + tid) * 4;
    if (l4 + 3 < L) {
        int4 ix = __ldg((const int4*)(index_x + l4));
        int4 iy = __ldg((const int4*)(index_y + l4));
        int4 px = __ldg((const int4*)(proj_x + l4));
        int4 py = __ldg((const int4*)(proj_y + l4));

        gather_add(imgTh, accTh, py.x * 1024 + px.x, ix.x * 1024 + iy.x);
        gather_add(imgTh, accTh, py.y * 1024 + px.y, ix.y * 1024 + iy.y);
        gather_add(imgTh, accTh, py.z * 1024 + px.z, ix.z * 1024 + iy.z);
        gather_add(imgTh, accTh, py.w * 1024 + px.w, ix.w * 1024 + iy.w);
    } else {
        for (int l = l4; l < L; l++) {
            int src = __ldg(proj_y + l) * 1024 + __ldg(proj_x + l);
            int dst = __ldg(index_x + l) * 1024 + __ldg(index_y + l);
            gather_add(imgTh, accTh, src, dst);
        }
    }
}

// Write out channels [8h, 8h+8) from accT_h. 2 positions/thread.
template <int HALF>
__device__ __forceinline__ void finish_block(float* __restrict__ out,
                                             int fb, int tid) {
    const float* __restrict__ accTh = (HALF == 0) ? g_accT0 : g_accT1;
    const size_t choff = (size_t)(HALF * 8) * HW;

    int p2 = (fb * 256 + tid) * 2;
    if (p2 >= HW) return;

    float4 v[4];
    const float4* a = (const float4*)(accTh + (size_t)p2 * 8);
#pragma unroll
    for (int i = 0; i < 4; i++) v[i] = a[i];
    const float* f = (const float*)v;  // f[j*8 + c] = acc[p2+j][c]
#pragma unroll
    for (int c = 0; c < 8; c++) {
        *(float2*)(out + choff + (size_t)c * HW + p2) =
            make_float2(f[c], f[8 + c]);
    }
}

// ---- kernels --------------------------------------------------------------

#define NPREP  (HW / 2 / 256)   // 2048 blocks per half-prep / half-finish

__global__ void __launch_bounds__(256) kA_prep0(const float* __restrict__ x,
                                                const float* __restrict__ img) {
    prep_block<0>(x, img, blockIdx.x, threadIdx.x);
}

// B: scatter half0 (2 of every 3 blocks) || prep half1 (1 of every 3)
__global__ void __launch_bounds__(256) kB(const float* __restrict__ x,
                                          const float* __restrict__ img,
                                          const int* __restrict__ index_x,
                                          const int* __restrict__ index_y,
                                          const int* __restrict__ proj_x,
                                          const int* __restrict__ proj_y,
                                          int L, int NS) {
    int g = blockIdx.x / 3, r = blockIdx.x % 3;
    if (r < 2) {
        int sb = g * 2 + r;
        if (sb < NS) scatter_block<0>(index_x, index_y, proj_x, proj_y, L, sb, threadIdx.x);
    } else {
        if (g < NPREP) prep_block<1>(x, img, g, threadIdx.x);
    }
}

// C: scatter half1 solo
__global__ void __launch_bounds__(256) kC_scatter1(const int* __restrict__ index_x,
                                                   const int* __restrict__ index_y,
                                                   const int* __restrict__ proj_x,
                                                   const int* __restrict__ proj_y,
                                                   int L) {
    scatter_block<1>(index_x, index_y, proj_x, proj_y, L, blockIdx.x, threadIdx.x);
}

// D: finish both halves, parity-interleaved.
__global__ void __launch_bounds__(256) kD_finish(float* __restrict__ out) {
    int g = blockIdx.x >> 1;
    if (blockIdx.x & 1) finish_block<1>(out, g, threadIdx.x);
    else                finish_block<0>(out, g, threadIdx.x);
}

extern "C" void kernel_launch(void* const* d_in, const int* in_sizes, int n_in,
                              void* d_out, int out_size) {
    const float* x       = (const float*)d_in[0];
    const float* img     = (const float*)d_in[1];
    const int*   index_x = (const int*)d_in[2];
    const int*   index_y = (const int*)d_in[3];
    const int*   proj_x  = (const int*)d_in[4];
    const int*   proj_y  = (const int*)d_in[5];
    float*       out     = (float*)d_out;

    const int L = in_sizes[2];

    int NS = (L / 4 + 255) / 256 + 1;                 // scatter blocks (tail-safe)
    int groups = ((NS + 1) / 2 > NPREP) ? (NS + 1) / 2 : NPREP;
    int NB = 3 * groups;

    kA_prep0<<<NPREP, 256>>>(x, img);
    kB<<<NB, 256>>>(x, img, index_x, index_y, proj_x, proj_y, L, NS);
    kC_scatter1<<<NS, 256>>>(index_x, index_y, proj_x, proj_y, L);
    kD_finish<<<2 * NPREP, 256>>>(out);
}

// round 12
// speedup vs baseline: 2.3492x; 1.4576x over previous
#include <cuda_runtime.h>
#include <cuda_fp16.h>

// out = x[0]; out[c, ix, iy] += img[c, proj_y, proj_x]
// R12: full-fp16 random phase, SINGLE scatter pass.
//   imgT[p][c] = f16(img[c][p])   (32 MB)
//   accT[p][c] = f16(x[0][c][p])  (32 MB)   -> 64 MB resident in L2
//   scatter: accT[dst][0..16) += imgT[src][0..16)
//            via 2x red.global.add.noftz.v4.f16x2 (16 B each)
//   finish:  out[c][p] = f32(accT[p][c])
// Indices read once. Error: f16 quantization of x+data+accum rounding
// ~3-4e-4 global rel err, under the 1e-3 threshold.

#define HW (1024 * 1024)

__device__ __half g_imgT[(size_t)HW * 16];
__device__ __half g_accT[(size_t)HW * 16];

__device__ __forceinline__ void red_add_v4_f16x2(__half* ptr, uint4 v) {
    asm volatile("red.global.add.noftz.v4.f16x2 [%0], {%1, %2, %3, %4};"
                 :: "l"(ptr), "r"(v.x), "r"(v.y), "r"(v.z), "r"(v.w)
                 : "memory");
}

// ---- prep: x -> accT (f16), img -> imgT (f16), 2 positions/thread ----------

__device__ __forceinline__ void prep_one(const float* __restrict__ src,
                                         __half* __restrict__ dstT,
                                         int p2) {
    float2 r[16];
#pragma unroll
    for (int c = 0; c < 16; c++)
        r[c] = __ldg((const float2*)(src + (size_t)c * HW + p2));

    __half2 h0[8], h1[8];
#pragma unroll
    for (int j = 0; j < 8; j++) {
        h0[j] = __floats2half2_rn(r[2 * j].x, r[2 * j + 1].x);  // position p2
        h1[j] = __floats2half2_rn(r[2 * j].y, r[2 * j + 1].y);  // position p2+1
    }
    uint4* d = (uint4*)(dstT + (size_t)p2 * 16);  // 2 pos x 32 B = 64 B contiguous
    d[0] = ((const uint4*)h0)[0];
    d[1] = ((const uint4*)h0)[1];
    d[2] = ((const uint4*)h1)[0];
    d[3] = ((const uint4*)h1)[1];
}

__global__ void __launch_bounds__(256) prep_kernel(const float* __restrict__ x,
                                                   const float* __restrict__ img) {
    int p2 = (blockIdx.x * 256 + threadIdx.x) * 2;
    if (p2 >= HW) return;
    prep_one(x,   g_accT, p2);
    prep_one(img, g_imgT, p2);
}

// ---- scatter: single pass over all 16 channels, 4 records/thread -----------

__device__ __forceinline__ void gather_add(int src, int dst) {
    const uint4* s = (const uint4*)(g_imgT + (size_t)src * 16);
    uint4 v0 = __ldg(s + 0);
    uint4 v1 = __ldg(s + 1);
    __half* d = g_accT + (size_t)dst * 16;
    red_add_v4_f16x2(d,     v0);
    red_add_v4_f16x2(d + 8, v1);
}

__global__ void __launch_bounds__(256) scatter_kernel(const int* __restrict__ index_x,
                                                      const int* __restrict__ index_y,
                                                      const int* __restrict__ proj_x,
                                                      const int* __restrict__ proj_y,
                                                      int L) {
    int l4 = (blockIdx.x * 256 + threadIdx.x) * 4;
    if (l4 + 3 < L) {
        int4 ix = __ldg((const int4*)(index_x + l4));
        int4 iy = __ldg((const int4*)(index_y + l4));
        int4 px = __ldg((const int4*)(proj_x + l4));
        int4 py = __ldg((const int4*)(proj_y + l4));

        gather_add(py.x * 1024 + px.x, ix.x * 1024 + iy.x);
        gather_add(py.y * 1024 + px.y, ix.y * 1024 + iy.y);
        gather_add(py.z * 1024 + px.z, ix.z * 1024 + iy.z);
        gather_add(py.w * 1024 + px.w, ix.w * 1024 + iy.w);
    } else {
        for (int l = l4; l < L; l++) {
            int src = __ldg(proj_y + l) * 1024 + __ldg(proj_x + l);
            int dst = __ldg(index_x + l) * 1024 + __ldg(index_y + l);
            gather_add(src, dst);
        }
    }
}

// ---- finish: accT (f16, position-major) -> out (f32, channel-major) --------

__global__ void __launch_bounds__(256) finish_kernel(float* __restrict__ out) {
    int p2 = (blockIdx.x * 256 + threadIdx.x) * 2;
    if (p2 >= HW) return;

    uint4 v[4];
    const uint4* a = (const uint4*)(g_accT + (size_t)p2 * 16);
#pragma unroll
    for (int i = 0; i < 4; i++) v[i] = a[i];
    const __half* h = (const __half*)v;  // h[j*16 + c] = acc[p2+j][c]
#pragma unroll
    for (int c = 0; c < 16; c++) {
        *(float2*)(out + (size_t)c * HW + p2) =
            make_float2(__half2float(h[c]), __half2float(h[16 + c]));
    }
}

extern "C" void kernel_launch(void* const* d_in, const int* in_sizes, int n_in,
                              void* d_out, int out_size) {
    const float* x       = (const float*)d_in[0];
    const float* img     = (const float*)d_in[1];
    const int*   index_x = (const int*)d_in[2];
    const int*   index_y = (const int*)d_in[3];
    const int*   proj_x  = (const int*)d_in[4];
    const int*   proj_y  = (const int*)d_in[5];
    float*       out     = (float*)d_out;

    const int L = in_sizes[2];

    int NP = HW / 2 / 256;                    // 2048
    int NS = (L / 4 + 255) / 256 + 1;         // tail-safe

    prep_kernel<<<NP, 256>>>(x, img);
    scatter_kernel<<<NS, 256>>>(index_x, index_y, proj_x, proj_y, L);
    finish_kernel<<<NP, 256>>>(out);
}

// round 13
// speedup vs baseline: 2.3793x; 1.0128x over previous
#include <cuda_runtime.h>
#include <cuda_fp16.h>

// out = x[0]; out[c, ix, iy] += img[c, proj_y, proj_x]
// R13: fp16 random phase, channel-split for overlap; x never quantized.
//   imgT_h[p][j] = f16(img[8h+j][p])   (16 MB per half)
//   accT_h[p][j] = 0                   (16 MB per half, f16 accumulator)
//   scatter_h: accT_h[dst] += imgT_h[src]  (ONE red.global.add.noftz.v4.f16x2
//              = 16 B per record-half; scatter is atomic-op bound ~130Kops/us)
//   finish_h: out[8h+j][p] = x[8h+j][p] + f32(accT_h[p][j])
// Schedule: A prep0 -> B scatter0||prep1 -> C scatter1||finish0 -> D finish1

#define HW (1024 * 1024)

__device__ __half g_imgT0[(size_t)HW * 8];
__device__ __half g_imgT1[(size_t)HW * 8];
__device__ __half g_accT0[(size_t)HW * 8];
__device__ __half g_accT1[(size_t)HW * 8];

__device__ __forceinline__ void red_add_v4_f16x2(__half* ptr, uint4 v) {
    asm volatile("red.global.add.noftz.v4.f16x2 [%0], {%1, %2, %3, %4};"
                 :: "l"(ptr), "r"(v.x), "r"(v.y), "r"(v.z), "r"(v.w)
                 : "memory");
}

// ---- role bodies ------------------------------------------------------------

// Transpose img chans [8h,8h+8) -> imgT_h (f16), zero accT_h. 2 pos/thread.
template <int HALF>
__device__ __forceinline__ void prep_block(const float* __restrict__ img,
                                           int pb, int tid) {
    __half* __restrict__ imgTh = (HALF == 0) ? g_imgT0 : g_imgT1;
    __half* __restrict__ accTh = (HALF == 0) ? g_accT0 : g_accT1;
    const size_t choff = (size_t)(HALF * 8) * HW;

    int p2 = (pb * 256 + tid) * 2;
    if (p2 >= HW) return;

    float2 r[8];
#pragma unroll
    for (int c = 0; c < 8; c++)
        r[c] = __ldg((const float2*)(img + choff + (size_t)c * HW + p2));

    __half2 h0[4], h1[4];
#pragma unroll
    for (int j = 0; j < 4; j++) {
        h0[j] = __floats2half2_rn(r[2 * j].x, r[2 * j + 1].x);  // pos p2
        h1[j] = __floats2half2_rn(r[2 * j].y, r[2 * j + 1].y);  // pos p2+1
    }
    uint4* d = (uint4*)(imgTh + (size_t)p2 * 8);  // 2 pos x 16 B contiguous
    d[0] = *(const uint4*)h0;
    d[1] = *(const uint4*)h1;

    uint4* z = (uint4*)(accTh + (size_t)p2 * 8);
    z[0] = make_uint4(0, 0, 0, 0);
    z[1] = make_uint4(0, 0, 0, 0);
}

// Scatter-add 4 records/thread within one half: 16 B gather + one 16 B red.
template <int HALF>
__device__ __forceinline__ void scatter_block(const int* __restrict__ index_x,
                                              const int* __restrict__ index_y,
                                              const int* __restrict__ proj_x,
                                              const int* __restrict__ proj_y,
                                              int L, int sb, int tid) {
    const __half* __restrict__ imgTh = (HALF == 0) ? g_imgT0 : g_imgT1;
    __half* __restrict__ accTh       = (HALF == 0) ? g_accT0 : g_accT1;

    int l4 = (sb * 256 + tid) * 4;
    if (l4 + 3 < L) {
        int4 ix = __ldg((const int4*)(index_x + l4));
        int4 iy = __ldg((const int4*)(index_y + l4));
        int4 px = __ldg((const int4*)(proj_x + l4));
        int4 py = __ldg((const int4*)(proj_y + l4));

        int s0 = py.x * 1024 + px.x, d0 = ix.x * 1024 + iy.x;
        int s1 = py.y * 1024 + px.y, d1 = ix.y * 1024 + iy.y;
        int s2 = py.z * 1024 + px.z, d2 = ix.z * 1024 + iy.z;
        int s3 = py.w * 1024 + px.w, d3 = ix.w * 1024 + iy.w;

        uint4 v0 = __ldg((const uint4*)(imgTh + (size_t)s0 * 8));
        uint4 v1 = __ldg((const uint4*)(imgTh + (size_t)s1 * 8));
        uint4 v2 = __ldg((const uint4*)(imgTh + (size_t)s2 * 8));
        uint4 v3 = __ldg((const uint4*)(imgTh + (size_t)s3 * 8));

        red_add_v4_f16x2(accTh + (size_t)d0 * 8, v0);
        red_add_v4_f16x2(accTh + (size_t)d1 * 8, v1);
        red_add_v4_f16x2(accTh + (size_t)d2 * 8, v2);
        red_add_v4_f16x2(accTh + (size_t)d3 * 8, v3);
    } else {
        for (int l = l4; l < L; l++) {
            int src = __ldg(proj_y + l) * 1024 + __ldg(proj_x + l);
            int dst = __ldg(index_x + l) * 1024 + __ldg(index_y + l);
            uint4 v = __ldg((const uint4*)(imgTh + (size_t)src * 8));
            red_add_v4_f16x2(accTh + (size_t)dst * 8, v);
        }
    }
}

// out[8h+j][p] = x[8h+j][p] + f32(accT_h[p][j]). 2 positions/thread.
template <int HALF>
__device__ __forceinline__ void finish_block(const float* __restrict__ x,
                                             float* __restrict__ out,
                                             int fb, int tid) {
    const __half* __restrict__ accTh = (HALF == 0) ? g_accT0 : g_accT1;
    const size_t choff = (size_t)(HALF * 8) * HW;

    int p2 = (fb * 256 + tid) * 2;
    if (p2 >= HW) return;

    uint4 v[2];
    v[0] = *(const uint4*)(accTh + (size_t)p2 * 8);
    v[1] = *(const uint4*)(accTh + (size_t)(p2 + 1) * 8);
    const __half* h = (const __half*)v;  // h[j*8 + c] = acc[p2+j][8h+c]

#pragma unroll
    for (int c = 0; c < 8; c++) {
        float2 xv = __ldg((const float2*)(x + choff + (size_t)c * HW + p2));
        *(float2*)(out + choff + (size_t)c * HW + p2) =
            make_float2(xv.x + __half2float(h[c]),
                        xv.y + __half2float(h[8 + c]));
    }
}

// ---- kernels --------------------------------------------------------------

#define NPREP  (HW / 2 / 256)   // 2048 blocks per half prep/finish

__global__ void __launch_bounds__(256) kA_prep0(const float* __restrict__ img) {
    prep_block<0>(img, blockIdx.x, threadIdx.x);
}

// B: scatter half0 (2 of every 3 blocks) || prep half1 (1 of every 3)
__global__ void __launch_bounds__(256) kB(const float* __restrict__ img,
                                          const int* __restrict__ index_x,
                                          const int* __restrict__ index_y,
                                          const int* __restrict__ proj_x,
                                          const int* __restrict__ proj_y,
                                          int L, int NS) {
    int g = blockIdx.x / 3, r = blockIdx.x % 3;
    if (r < 2) {
        int sb = g * 2 + r;
        if (sb < NS) scatter_block<0>(index_x, index_y, proj_x, proj_y, L, sb, threadIdx.x);
    } else {
        if (g < NPREP) prep_block<1>(img, g, threadIdx.x);
    }
}

// C: scatter half1 (2:1) || finish half0
__global__ void __launch_bounds__(256) kC(const float* __restrict__ x,
                                          float* __restrict__ out,
                                          const int* __restrict__ index_x,
                                          const int* __restrict__ index_y,
                                          const int* __restrict__ proj_x,
                                          const int* __restrict__ proj_y,
                                          int L, int NS) {
    int g = blockIdx.x / 3, r = blockIdx.x % 3;
    if (r < 2) {
        int sb = g * 2 + r;
        if (sb < NS) scatter_block<1>(index_x, index_y, proj_x, proj_y, L, sb, threadIdx.x);
    } else {
        if (g < NPREP) finish_block<0>(x, out, g, threadIdx.x);
    }
}

__global__ void __launch_bounds__(256) kD_finish1(const float* __restrict__ x,
                                                  float* __restrict__ out) {
    finish_block<1>(x, out, blockIdx.x, threadIdx.x);
}

extern "C" void kernel_launch(void* const* d_in, const int* in_sizes, int n_in,
                              void* d_out, int out_size) {
    const float* x       = (const float*)d_in[0];
    const float* img     = (const float*)d_in[1];
    const int*   index_x = (const int*)d_in[2];
    const int*   index_y = (const int*)d_in[3];
    const int*   proj_x  = (const int*)d_in[4];
    const int*   proj_y  = (const int*)d_in[5];
    float*       out     = (float*)d_out;

    const int L = in_sizes[2];

    int NS = (L / 4 + 255) / 256 + 1;                 // scatter blocks (tail-safe)
    int groups = ((NS + 1) / 2 > NPREP) ? (NS + 1) / 2 : NPREP;
    int NB = 3 * groups;

    kA_prep0<<<NPREP, 256>>>(img);
    kB<<<NB, 256>>>(img, index_x, index_y, proj_x, proj_y, L, NS);
    kC<<<NB, 256>>>(x, out, index_x, index_y, proj_x, proj_y, L, NS);
    kD_finish1<<<NPREP, 256>>>(x, out);
}